// round 1
// baseline (speedup 1.0000x reference)
#include <cuda_runtime.h>
#include <math_constants.h>

// Problem constants (fixed by the dataset: h is (16, 2048, 64) fp32, K = 16)
#define NS   16
#define NP   2048
#define DIMS 64
#define KNN  16
#define TI   128   // i-rows per block (== blockDim.x)
#define TJ   128   // j-rows per shared tile

__global__ __launch_bounds__(TI)
void knn_kernel(const float* __restrict__ h, float* __restrict__ out) {
    const int b  = blockIdx.x;            // sample
    const int i  = blockIdx.y * TI + threadIdx.x;  // point index within sample
    const float* __restrict__ hb = h + (size_t)b * NP * DIMS;

    __shared__ float sj[TJ][DIMS];        // j tile, 32 KB
    __shared__ float sx2[TJ];             // ||h_j||^2 for the tile

    // ---- load this thread's row into registers + compute ||h_i||^2 ----
    float4 hi[DIMS / 4];
    const float4* hrow = reinterpret_cast<const float4*>(hb + (size_t)i * DIMS);
    float x2i = 0.0f;
    #pragma unroll
    for (int d = 0; d < DIMS / 4; ++d) {
        hi[d] = hrow[d];
        x2i += hi[d].x * hi[d].x + hi[d].y * hi[d].y
             + hi[d].z * hi[d].z + hi[d].w * hi[d].w;
    }

    // ---- running top-K (sorted ascending by (dist, idx)) ----
    float bd[KNN];
    int   bi[KNN];
    #pragma unroll
    for (int k = 0; k < KNN; ++k) { bd[k] = CUDART_INF_F; bi[k] = 0x7fffffff; }

    for (int j0 = 0; j0 < NP; j0 += TJ) {
        __syncthreads();
        // cooperative tile load (coalesced float4)
        {
            float4*       s4 = reinterpret_cast<float4*>(&sj[0][0]);
            const float4* g4 = reinterpret_cast<const float4*>(hb + (size_t)j0 * DIMS);
            #pragma unroll
            for (int t = threadIdx.x; t < TJ * DIMS / 4; t += TI) s4[t] = g4[t];
        }
        __syncthreads();
        // per-row ||h_j||^2 (one thread per row; TI == TJ)
        {
            const int jj = threadIdx.x;
            float s = 0.0f;
            #pragma unroll
            for (int d = 0; d < DIMS; ++d) s += sj[jj][d] * sj[jj][d];
            sx2[jj] = s;
        }
        __syncthreads();

        // ---- distances to every j in the tile ----
        for (int jj = 0; jj < TJ; ++jj) {
            const float4* row = reinterpret_cast<const float4*>(sj[jj]);
            float a0 = 0.f, a1 = 0.f, a2 = 0.f, a3 = 0.f;
            #pragma unroll
            for (int d = 0; d < DIMS / 4; ++d) {
                float4 v = row[d];          // broadcast LDS.128 (same addr all lanes)
                a0 = fmaf(hi[d].x, v.x, a0);
                a1 = fmaf(hi[d].y, v.y, a1);
                a2 = fmaf(hi[d].z, v.z, a2);
                a3 = fmaf(hi[d].w, v.w, a3);
            }
            const float dot  = (a0 + a1) + (a2 + a3);
            const float dist = fmaf(-2.0f, dot, x2i + sx2[jj]);
            const int   j    = j0 + jj;

            // insert if better than current worst; lexicographic (dist, idx)
            bool ins = (dist < bd[KNN - 1]) ||
                       (dist == bd[KNN - 1] && j < bi[KNN - 1]);
            if (ins) {
                bd[KNN - 1] = dist;
                bi[KNN - 1] = j;
                #pragma unroll
                for (int s = KNN - 1; s > 0; --s) {
                    bool sw = (bd[s] < bd[s - 1]) ||
                              (bd[s] == bd[s - 1] && bi[s] < bi[s - 1]);
                    if (sw) {
                        float td = bd[s]; bd[s] = bd[s - 1]; bd[s - 1] = td;
                        int   ti = bi[s]; bi[s] = bi[s - 1]; bi[s - 1] = ti;
                    }
                }
            }
        }
    }

    // ---- emit: [knn_dist | dst | src], all as float32 ----
    const size_t row   = (size_t)b * NP + i;
    const size_t sect  = (size_t)NS * NP * KNN;
    float* od   = out + row * KNN;
    float* odst = out + sect + row * KNN;
    float* osrc = out + 2 * sect + row * KNN;
    const int off = b * NP;
    #pragma unroll
    for (int k = 0; k < KNN; ++k) {
        od[k]   = bd[k];
        odst[k] = (float)(bi[k] + off);
        osrc[k] = (float)(i + off);
    }
}

extern "C" void kernel_launch(void* const* d_in, const int* in_sizes, int n_in,
                              void* d_out, int out_size) {
    (void)in_sizes; (void)n_in; (void)out_size;
    const float* h = (const float*)d_in[0];   // (16, 2048, 64) fp32; d_in[1] is K=16 (hardcoded)
    float* out = (float*)d_out;
    dim3 grid(NS, NP / TI);
    knn_kernel<<<grid, TI>>>(h, out);
}

// round 2
// speedup vs baseline: 1.2409x; 1.2409x over previous
#include <cuda_runtime.h>
#include <math_constants.h>

#define NS   16
#define NP   2048
#define DIMS 64
#define KNN  16
#define TI   32    // one warp per block
#define TJ   64    // j-rows per shared tile
#define BUF  4     // candidate buffer slots per lane

typedef unsigned long long ull;

__device__ __forceinline__ void upk(float &lo, float &hi_, ull v) {
    asm("mov.b64 {%0, %1}, %2;" : "=f"(lo), "=f"(hi_) : "l"(v));
}
__device__ __forceinline__ void ffma2(ull &d, ull a, ull b) {
    asm("fma.rn.f32x2 %0, %1, %2, %3;" : "=l"(d) : "l"(a), "l"(b), "l"(d));
}

// replace-max insert into unsorted top-K kept in registers
__device__ __forceinline__ void insert16(float bd[KNN], int bidx[KNN],
                                         float &worst, int &wslot,
                                         float d, int j) {
    if (d < worst) {
        #pragma unroll
        for (int k = 0; k < KNN; ++k) {
            if (k == wslot) { bd[k] = d; bidx[k] = j; }
        }
        float mv = bd[0]; int mj = bidx[0]; int ms = 0;
        #pragma unroll
        for (int k = 1; k < KNN; ++k) {
            bool g = (bd[k] > mv) || (bd[k] == mv && bidx[k] > mj);
            if (g) { mv = bd[k]; mj = bidx[k]; ms = k; }
        }
        worst = mv; wslot = ms;
    }
}

__global__ __launch_bounds__(TI)
void knn_kernel(const float* __restrict__ h, float* __restrict__ out) {
    const int b = blockIdx.x;
    const int i = blockIdx.y * TI + threadIdx.x;
    const float* __restrict__ hb = h + (size_t)b * NP * DIMS;

    __shared__ ulonglong2 sj[TJ][DIMS / 4];   // 16 KB, 16B-aligned rows
    __shared__ float sx2[TJ];

    // ---- this thread's i-row, packed as f32x2 pairs ----
    ull hr[DIMS / 2];
    const ulonglong2* hrow = reinterpret_cast<const ulonglong2*>(hb + (size_t)i * DIMS);
    #pragma unroll
    for (int d = 0; d < DIMS / 4; ++d) { ulonglong2 t = hrow[d]; hr[2*d] = t.x; hr[2*d+1] = t.y; }
    float x2i = 0.0f;
    #pragma unroll
    for (int d = 0; d < DIMS / 2; ++d) { float a, c; upk(a, c, hr[d]); x2i += a*a + c*c; }

    // ---- unsorted top-K + max tracking ----
    float bd[KNN]; int bidx[KNN];
    #pragma unroll
    for (int k = 0; k < KNN; ++k) { bd[k] = CUDART_INF_F; bidx[k] = 0x7fffffff; }
    float worst = CUDART_INF_F; int wslot = 0;

    // ---- candidate buffer ----
    float cd[BUF]; int cj[BUF]; int c = 0;
    #pragma unroll
    for (int s = 0; s < BUF; ++s) { cd[s] = 0.f; cj[s] = 0; }

    for (int j0 = 0; j0 < NP; j0 += TJ) {
        __syncwarp();
        // cooperative tile load (128-bit)
        {
            ulonglong2*       s4 = &sj[0][0];
            const ulonglong2* g4 = reinterpret_cast<const ulonglong2*>(hb + (size_t)j0 * DIMS);
            #pragma unroll
            for (int t = threadIdx.x; t < TJ * DIMS / 4; t += TI) s4[t] = g4[t];
        }
        __syncwarp();
        // ||h_j||^2 for the tile (2 rows per thread)
        #pragma unroll
        for (int r = threadIdx.x; r < TJ; r += TI) {
            float s = 0.0f;
            #pragma unroll
            for (int d = 0; d < DIMS / 4; ++d) {
                ulonglong2 v = sj[r][d];
                float a, bq, cq, e; upk(a, bq, v.x); upk(cq, e, v.y);
                s += a*a + bq*bq + cq*cq + e*e;
            }
            sx2[r] = s;
        }
        __syncwarp();

        for (int jj = 0; jj < TJ; ++jj) {
            // 64-dim dot as 32 packed FMAs, 4 independent chains
            ull a0 = 0ull, a1 = 0ull, a2 = 0ull, a3 = 0ull;  // (0.f,0.f) bit pattern
            #pragma unroll
            for (int d = 0; d < DIMS / 8; ++d) {
                ulonglong2 v = sj[jj][2*d];
                ulonglong2 w = sj[jj][2*d + 1];
                ffma2(a0, hr[4*d + 0], v.x);
                ffma2(a1, hr[4*d + 1], v.y);
                ffma2(a2, hr[4*d + 2], w.x);
                ffma2(a3, hr[4*d + 3], w.y);
            }
            float f0,f1,f2,f3,f4,f5,f6,f7;
            upk(f0, f1, a0); upk(f2, f3, a1); upk(f4, f5, a2); upk(f6, f7, a3);
            const float dot  = ((f0 + f1) + (f2 + f3)) + ((f4 + f5) + (f6 + f7));
            const float dist = fmaf(-2.0f, dot, x2i + sx2[jj]);
            const int   jg   = j0 + jj;

            // cheap filter into buffer (strict <; ascending j handles ties)
            const bool take = dist < worst;
            if (take) {
                #pragma unroll
                for (int s = 0; s < BUF; ++s) {
                    if (s == c) { cd[s] = dist; cj[s] = jg; }
                }
                ++c;
            }
            // rare warp-wide drain
            if (__any_sync(0xffffffffu, c == BUF)) {
                #pragma unroll
                for (int s = 0; s < BUF; ++s) {
                    if (s < c) insert16(bd, bidx, worst, wslot, cd[s], cj[s]);
                }
                c = 0;
            }
        }
    }
    // final drain
    #pragma unroll
    for (int s = 0; s < BUF; ++s) {
        if (s < c) insert16(bd, bidx, worst, wslot, cd[s], cj[s]);
    }

    // sort ascending by (dist, idx): odd-even transposition, 16 passes
    #pragma unroll
    for (int p = 0; p < KNN; ++p) {
        #pragma unroll
        for (int k = (p & 1); k + 1 < KNN; k += 2) {
            bool sw = (bd[k] > bd[k+1]) || (bd[k] == bd[k+1] && bidx[k] > bidx[k+1]);
            if (sw) {
                float td = bd[k];  bd[k] = bd[k+1];   bd[k+1] = td;
                int   ti = bidx[k]; bidx[k] = bidx[k+1]; bidx[k+1] = ti;
            }
        }
    }

    // ---- emit: [knn_dist | dst | src], all float32 ----
    const size_t row  = (size_t)b * NP + i;
    const size_t sect = (size_t)NS * NP * KNN;
    float* od   = out + row * KNN;
    float* odst = out + sect + row * KNN;
    float* osrc = out + 2 * sect + row * KNN;
    const int off = b * NP;
    #pragma unroll
    for (int k = 0; k < KNN; ++k) {
        od[k]   = bd[k];
        odst[k] = (float)(bidx[k] + off);
        osrc[k] = (float)(i + off);
    }
}

extern "C" void kernel_launch(void* const* d_in, const int* in_sizes, int n_in,
                              void* d_out, int out_size) {
    (void)in_sizes; (void)n_in; (void)out_size;
    const float* h = (const float*)d_in[0];   // (16, 2048, 64) fp32; K=16 hardcoded
    float* out = (float*)d_out;
    dim3 grid(NS, NP / TI);
    knn_kernel<<<grid, TI>>>(h, out);
}